// round 9
// baseline (speedup 1.0000x reference)
#include <cuda_runtime.h>
#include <cuda_bf16.h>
#include <cstddef>

#define T_STEPS 2048
#define BATCH   64
#define HID     128
#define GATES   512          // 4*HID
#define RK      88           // k-values in registers (as pairs)
#define RKP     (RK/2)       // 44 register pairs
#define SK      (HID - RK)   // 40 k-values in smem
#define SKP     (SK/2)       // 20 smem pairs
#define WROW    22           // padded ws row stride in pairs (176 B, conflict-free)
#define NSM     148
#define NWORK   (NSM - BATCH)   // 84 gemm worker CTAs

typedef unsigned long long ull;

// ---- packed fp32x2 helpers (sm_100+) --------------------------------------
__device__ __forceinline__ ull ffma2(ull a, ull b, ull c) {
    ull d;
    asm("fma.rn.f32x2 %0, %1, %2, %3;" : "=l"(d) : "l"(a), "l"(b), "l"(c));
    return d;
}
__device__ __forceinline__ ull pack2(float lo, float hi) {
    ull r; asm("mov.b64 %0, {%1, %2};" : "=l"(r) : "f"(lo), "f"(hi)); return r;
}
__device__ __forceinline__ float2 unpack2(ull v) {
    float2 f; asm("mov.b64 {%0, %1}, %2;" : "=f"(f.x), "=f"(f.y) : "l"(v)); return f;
}

// Scratch (device globals; no allocations allowed)
__device__ float g_gxA[(size_t)BATCH * T_STEPS * GATES];  // 256 MB
__device__ float g_gxB[(size_t)BATCH * T_STEPS * GATES];  // 256 MB
__device__ float g_h  [(size_t)BATCH * T_STEPS * HID];    // 64 MB
__device__ int   g_prog[3 * BATCH];                        // rec progress per layer

// ---------------------------------------------------------------------------
// GEMM tile machinery (bf16 3-product split, fp32 acc, ldmatrix)
// ---------------------------------------------------------------------------
#define SR 136   // padded bf16 row stride

__device__ __forceinline__ void mma_bf16(float* d, const unsigned* a, const unsigned* b) {
    asm volatile(
        "mma.sync.aligned.m16n8k16.row.col.f32.bf16.bf16.f32 "
        "{%0,%1,%2,%3}, {%4,%5,%6,%7}, {%8,%9}, {%0,%1,%2,%3};"
        : "+f"(d[0]), "+f"(d[1]), "+f"(d[2]), "+f"(d[3])
        : "r"(a[0]), "r"(a[1]), "r"(a[2]), "r"(a[3]), "r"(b[0]), "r"(b[1]));
}
__device__ __forceinline__ void ldsm_x4(unsigned* r, unsigned addr) {
    asm volatile("ldmatrix.sync.aligned.m8n8.x4.shared.b16 {%0,%1,%2,%3}, [%4];"
                 : "=r"(r[0]), "=r"(r[1]), "=r"(r[2]), "=r"(r[3]) : "r"(addr));
}

// One 128x128 tile: out[brow..][bcol..] = A[brow..][0..128) * W[bcol..][.]^T + bias
__device__ void gemm_tile(const float* __restrict__ A, const float* __restrict__ W,
                          const float* __restrict__ bih, const float* __restrict__ bhh,
                          float* __restrict__ out, int brow, int bcol, char* gsm)
{
    __nv_bfloat16* a_hi = (__nv_bfloat16*)gsm;                  // [128][SR]
    __nv_bfloat16* a_lo = a_hi + 128 * SR;
    __nv_bfloat16* w_hi = a_lo + 128 * SR;
    __nv_bfloat16* w_lo = w_hi + 128 * SR;
    float*         bias_s = (float*)(w_lo + 128 * SR);          // [128]

    const int tid = threadIdx.x;
    if (tid < 128) bias_s[tid] = bih[bcol + tid] + bhh[bcol + tid];

    {
        const int row = tid >> 1;
        const int cb  = (tid & 1) * 64;
        const float* Ar = A + (size_t)(brow + row) * HID + cb;
        const float* Wr = W + (size_t)(bcol + row) * HID + cb;
        __nv_bfloat16* ah = a_hi + row * SR + cb;
        __nv_bfloat16* al = a_lo + row * SR + cb;
        __nv_bfloat16* wh = w_hi + row * SR + cb;
        __nv_bfloat16* wl = w_lo + row * SR + cb;
#pragma unroll 4
        for (int c = 0; c < 64; c += 4) {
            float4 v = *(const float4*)(Ar + c);
            __nv_bfloat16 hx = __float2bfloat16_rn(v.x);
            __nv_bfloat16 hy = __float2bfloat16_rn(v.y);
            __nv_bfloat16 hz = __float2bfloat16_rn(v.z);
            __nv_bfloat16 hw = __float2bfloat16_rn(v.w);
            __nv_bfloat162 H0; H0.x = hx; H0.y = hy;
            __nv_bfloat162 H1; H1.x = hz; H1.y = hw;
            __nv_bfloat162 L0 = __floats2bfloat162_rn(v.x - __bfloat162float(hx),
                                                      v.y - __bfloat162float(hy));
            __nv_bfloat162 L1 = __floats2bfloat162_rn(v.z - __bfloat162float(hz),
                                                      v.w - __bfloat162float(hw));
            *(__nv_bfloat162*)(ah + c)     = H0;
            *(__nv_bfloat162*)(ah + c + 2) = H1;
            *(__nv_bfloat162*)(al + c)     = L0;
            *(__nv_bfloat162*)(al + c + 2) = L1;

            float4 u = *(const float4*)(Wr + c);
            __nv_bfloat16 gx = __float2bfloat16_rn(u.x);
            __nv_bfloat16 gy = __float2bfloat16_rn(u.y);
            __nv_bfloat16 gz = __float2bfloat16_rn(u.z);
            __nv_bfloat16 gw = __float2bfloat16_rn(u.w);
            __nv_bfloat162 G0; G0.x = gx; G0.y = gy;
            __nv_bfloat162 G1; G1.x = gz; G1.y = gw;
            __nv_bfloat162 M0 = __floats2bfloat162_rn(u.x - __bfloat162float(gx),
                                                      u.y - __bfloat162float(gy));
            __nv_bfloat162 M1 = __floats2bfloat162_rn(u.z - __bfloat162float(gz),
                                                      u.w - __bfloat162float(gw));
            *(__nv_bfloat162*)(wh + c)     = G0;
            *(__nv_bfloat162*)(wh + c + 2) = G1;
            *(__nv_bfloat162*)(wl + c)     = M0;
            *(__nv_bfloat162*)(wl + c + 2) = M1;
        }
    }
    __syncthreads();

    const int wid    = tid >> 5;
    const int lane   = tid & 31;
    const int warp_m = wid >> 1;
    const int warp_n = wid & 1;
    const int m_base = warp_m * 32;
    const int n_base = warp_n * 64;

    const unsigned a_hi_s = (unsigned)__cvta_generic_to_shared(a_hi);
    const unsigned a_lo_s = (unsigned)__cvta_generic_to_shared(a_lo);
    const unsigned w_hi_s = (unsigned)__cvta_generic_to_shared(w_hi);
    const unsigned w_lo_s = (unsigned)__cvta_generic_to_shared(w_lo);

    const int arow  = m_base + (lane & 15);
    const int akoff = (lane >> 4) * 8;
    const int gsel  = lane >> 3;
    const int brow_ = n_base + ((gsel >> 1) & 1) * 8 + (lane & 7);
    const int bkoff = (gsel & 1) * 8;

    float d[2][8][4];
#pragma unroll
    for (int mi = 0; mi < 2; mi++)
#pragma unroll
        for (int ni = 0; ni < 8; ni++)
#pragma unroll
            for (int e = 0; e < 4; e++) d[mi][ni][e] = 0.f;

#pragma unroll
    for (int k0 = 0; k0 < HID; k0 += 16) {
        unsigned ah[2][4], al[2][4];
#pragma unroll
        for (int mi = 0; mi < 2; mi++) {
            unsigned off = (unsigned)(((arow + mi * 16) * SR + akoff + k0) * 2);
            ldsm_x4(ah[mi], a_hi_s + off);
            ldsm_x4(al[mi], a_lo_s + off);
        }
        unsigned bh[4][4], bl[4][4];
#pragma unroll
        for (int nb = 0; nb < 4; nb++) {
            unsigned off = (unsigned)(((brow_ + nb * 16) * SR + bkoff + k0) * 2);
            ldsm_x4(bh[nb], w_hi_s + off);
            ldsm_x4(bl[nb], w_lo_s + off);
        }
#pragma unroll
        for (int mi = 0; mi < 2; mi++)
#pragma unroll
            for (int nb = 0; nb < 4; nb++) {
                mma_bf16(d[mi][2 * nb],     ah[mi], &bh[nb][0]);
                mma_bf16(d[mi][2 * nb],     ah[mi], &bl[nb][0]);
                mma_bf16(d[mi][2 * nb],     al[mi], &bh[nb][0]);
                mma_bf16(d[mi][2 * nb + 1], ah[mi], &bh[nb][2]);
                mma_bf16(d[mi][2 * nb + 1], ah[mi], &bl[nb][2]);
                mma_bf16(d[mi][2 * nb + 1], al[mi], &bh[nb][2]);
            }
    }

    const int tr = lane >> 2;
    const int tc = (lane & 3) * 2;
#pragma unroll
    for (int mi = 0; mi < 2; mi++) {
        int gr0 = brow + m_base + mi * 16 + tr;
#pragma unroll
        for (int ni = 0; ni < 8; ni++) {
            int lc = n_base + ni * 8 + tc;
            float2 bv = *(const float2*)&bias_s[lc];
            float2 o0 = {d[mi][ni][0] + bv.x, d[mi][ni][1] + bv.y};
            float2 o1 = {d[mi][ni][2] + bv.x, d[mi][ni][3] + bv.y};
            *(float2*)(out + (size_t)gr0 * GATES + bcol + lc)       = o0;
            *(float2*)(out + (size_t)(gr0 + 8) * GATES + bcol + lc) = o1;
        }
    }
}

// Standalone layer-0 GEMM over the whole input
__global__ __launch_bounds__(256) void gemm0_kernel(
    const float* __restrict__ A, const float* __restrict__ W,
    const float* __restrict__ bih, const float* __restrict__ bhh)
{
    extern __shared__ char gsm[];
    gemm_tile(A, W, bih, bhh, g_gxA, blockIdx.x * 128, blockIdx.y * 128, gsm);
}

// ---------------------------------------------------------------------------
// Recurrence body: one CTA per batch row, 256 threads, two barriers/step.
// Weights: k<RK as packed pairs in registers; k>=RK in smem ROW-MAJOR
// (ws[row][pair], 22-pair padded stride) so each thread streams its own
// rows with LDS.128. h read as LDS.128 broadcasts (2 pairs/load).
// ---------------------------------------------------------------------------
__device__ __forceinline__ float sigm(float x) {
    return __fdividef(1.f, 1.f + __expf(-x));
}
__device__ __forceinline__ float tanh_fast(float x) {
    float e = __expf(2.f * x);
    return 1.f - __fdividef(2.f, e + 1.f);
}

__device__ void rec_body(const float* __restrict__ whh, const float* __restrict__ gx,
                         int* __restrict__ prog, int b, char* smraw)
{
    ull*   ws2 = (ull*)smraw;                    // [512][WROW] row-major weight pairs
    float* g_s = (float*)(ws2 + 512 * WROW);     // 512 gate pre-activations
    float* h_s = g_s + GATES;                    // 128 hidden state (16B aligned)

    const int tid = threadIdx.x;
    const int r0  = tid;
    const int r1  = tid + 256;

    ull wa2[RKP], wb2[RKP];
    {
        const ull* wp0 = (const ull*)(whh + (size_t)r0 * HID);
        const ull* wp1 = (const ull*)(whh + (size_t)r1 * HID);
#pragma unroll
        for (int q = 0; q < RKP; q++) { wa2[q] = wp0[q]; wb2[q] = wp1[q]; }
    }
    // Smem weights, row-major: ws2[r*WROW + p] = pair (RKP+p) of gate-row r
    for (int idx = tid; idx < 512 * SKP; idx += 256) {
        int r = idx / SKP, p = idx % SKP;
        ws2[r * WROW + p] = ((const ull*)(whh + (size_t)r * HID))[RKP + p];
    }
    if (tid < HID) h_s[tid] = 0.f;
    float c = 0.f;
    __syncthreads();

    const float* gxb = gx  + (size_t)b * T_STEPS * GATES;
    float*       hb  = g_h + (size_t)b * T_STEPS * HID;
    const ull* wr0 = ws2 + r0 * WROW;
    const ull* wr1 = ws2 + r1 * WROW;

    float nga = gxb[r0];
    float ngb = gxb[r1];

    for (int t = 0; t < T_STEPS; t++) {
        ull acc0a = pack2(nga, 0.f), acc0b = 0ULL;
        ull acc1a = pack2(ngb, 0.f), acc1b = 0ULL;
        if (t + 1 < T_STEPS) {
            nga = __ldg(gxb + (size_t)(t + 1) * GATES + r0);
            ngb = __ldg(gxb + (size_t)(t + 1) * GATES + r1);
        }
        const ull* h2 = (const ull*)h_s;
#pragma unroll
        for (int q = 0; q < RKP - 1; q += 2) {
            ulonglong2 hq = *(const ulonglong2*)(h2 + q);
            acc0a = ffma2(hq.x, wa2[q],     acc0a);
            acc1a = ffma2(hq.x, wb2[q],     acc1a);
            acc0b = ffma2(hq.y, wa2[q + 1], acc0b);
            acc1b = ffma2(hq.y, wb2[q + 1], acc1b);
        }
#pragma unroll
        for (int p = 0; p < SKP; p += 2) {
            ulonglong2 hq = *(const ulonglong2*)(h2 + RKP + p);
            ulonglong2 wav = *(const ulonglong2*)(wr0 + p);
            ulonglong2 wbv = *(const ulonglong2*)(wr1 + p);
            acc0a = ffma2(hq.x, wav.x, acc0a);
            acc0b = ffma2(hq.y, wav.y, acc0b);
            acc1a = ffma2(hq.x, wbv.x, acc1a);
            acc1b = ffma2(hq.y, wbv.y, acc1b);
        }
        float2 v0a = unpack2(acc0a), v0b = unpack2(acc0b);
        float2 v1a = unpack2(acc1a), v1b = unpack2(acc1b);
        g_s[r0] = (v0a.x + v0b.x) + (v0a.y + v0b.y);
        g_s[r1] = (v1a.x + v1b.x) + (v1a.y + v1b.y);
        __syncthreads();
        if (tid < 128) {
            float i_ = sigm(g_s[tid]);
            float f_ = sigm(g_s[tid + 128]);
            float g_ = tanh_fast(g_s[tid + 256]);
            float o_ = sigm(g_s[tid + 384]);
            c = fmaf(f_, c, i_ * g_);
            float hv = o_ * tanh_fast(c);
            h_s[tid] = hv;
            hb[(size_t)t * HID + tid] = hv;
        }
        __syncthreads();
        if ((t & 31) == 31 && tid == 0) {
            __threadfence();
            atomicExch(prog + b, t + 1);
        }
    }
}

// ---------------------------------------------------------------------------
// GEMM worker: persistent CTA computing next layer's gx tiles, paced by the
// recurrence's progress counters. Tiles ordered t-chunk-major.
// ---------------------------------------------------------------------------
__device__ void gemm_worker(const float* __restrict__ W,
                            const float* __restrict__ bih, const float* __restrict__ bhh,
                            float* __restrict__ out, int* __restrict__ prog,
                            int worker, char* gsm)
{
    const int tid = threadIdx.x;
    const int NT = 16 * BATCH * 4;   // 16 t-chunks * 64 batch * 4 col tiles = 4096
    for (int idx = worker; idx < NT; idx += NWORK) {
        int tt  = idx >> 8;          // 0..15
        int rem = idx & 255;
        int b   = rem >> 2;          // 0..63
        int cy  = rem & 3;           // 0..3
        int need = (tt + 1) * 128;
        if (tid == 0) {
            unsigned v;
            while (true) {
                asm volatile("ld.global.cg.u32 %0, [%1];" : "=r"(v) : "l"(prog + b));
                if ((int)v >= need) break;
                __nanosleep(256);
            }
            __threadfence();
        }
        __syncthreads();
        gemm_tile(g_h, W, bih, bhh, out, b * T_STEPS + tt * 128, cy * 128, gsm);
        __syncthreads();
    }
}

// ---------------------------------------------------------------------------
// Combined layer kernel: blocks [0,64) run the recurrence for layer l,
// blocks [64,148) stream next layer's input GEMM.
// ---------------------------------------------------------------------------
__global__ __launch_bounds__(256, 1) void layer_kernel(
    const float* __restrict__ whh, const float* __restrict__ gx_in,
    const float* __restrict__ wih_next, const float* __restrict__ bih_next,
    const float* __restrict__ bhh_next, float* __restrict__ gx_out,
    int* __restrict__ prog, int do_gemm)
{
    extern __shared__ char smraw[];
    if (blockIdx.x < BATCH) {
        rec_body(whh, gx_in, prog, blockIdx.x, smraw);
    } else if (do_gemm) {
        gemm_worker(wih_next, bih_next, bhh_next, gx_out, prog,
                    blockIdx.x - BATCH, smraw);
    }
}

// ---------------------------------------------------------------------------
// MLP head: h_last[64,128] -> 64 -> 32 -> 10 (all linear)
// ---------------------------------------------------------------------------
__global__ __launch_bounds__(256) void mlp_kernel(
    const float* __restrict__ w1, const float* __restrict__ b1,
    const float* __restrict__ w2, const float* __restrict__ b2,
    const float* __restrict__ w3, const float* __restrict__ b3,
    float* __restrict__ out)
{
    extern __shared__ float sm[];
    float* hs = sm;          // 64*128, later reused for y2 (64*32)
    float* y1 = sm + 8192;   // 64*64

    const int tid = threadIdx.x;
    for (int idx = tid; idx < 8192; idx += 256) {
        int b = idx >> 7, j = idx & 127;
        hs[idx] = g_h[(size_t)b * T_STEPS * HID + (size_t)(T_STEPS - 1) * HID + j];
    }
    __syncthreads();
    for (int idx = tid; idx < 4096; idx += 256) {
        int b = idx >> 6, o = idx & 63;
        float s = b1[o];
#pragma unroll 8
        for (int k = 0; k < 128; k++) s = fmaf(hs[b * 128 + k], w1[o * 128 + k], s);
        y1[idx] = s;
    }
    __syncthreads();
    for (int idx = tid; idx < 2048; idx += 256) {
        int b = idx >> 5, o = idx & 31;
        float s = b2[o];
#pragma unroll 8
        for (int k = 0; k < 64; k++) s = fmaf(y1[b * 64 + k], w2[o * 64 + k], s);
        hs[idx] = s;  // reuse hs as y2 [64,32]
    }
    __syncthreads();
    for (int idx = tid; idx < 640; idx += 256) {
        int b = idx / 10, o = idx % 10;
        float s = b3[o];
#pragma unroll
        for (int k = 0; k < 32; k++) s = fmaf(hs[b * 32 + k], w3[o * 32 + k], s);
        out[idx] = s;
    }
}

// ---------------------------------------------------------------------------
extern "C" void kernel_launch(void* const* d_in, const int* in_sizes, int n_in,
                              void* d_out, int out_size)
{
    (void)in_sizes; (void)n_in; (void)out_size;
    const float* x   = (const float*)d_in[0];
    const float* wih = (const float*)d_in[1];
    const float* whh = (const float*)d_in[2];
    const float* bih = (const float*)d_in[3];
    const float* bhh = (const float*)d_in[4];
    const float* w1  = (const float*)d_in[5];
    const float* b1  = (const float*)d_in[6];
    const float* w2  = (const float*)d_in[7];
    const float* b2  = (const float*)d_in[8];
    const float* w3  = (const float*)d_in[9];
    const float* b3  = (const float*)d_in[10];

    void *pA = nullptr, *pB = nullptr, *pP = nullptr;
    cudaGetSymbolAddress(&pA, g_gxA);
    cudaGetSymbolAddress(&pB, g_gxB);
    cudaGetSymbolAddress(&pP, g_prog);
    float* bufA = (float*)pA;
    float* bufB = (float*)pB;
    int*   prog = (int*)pP;

    const int GEMM_SMEM = 4 * 128 * SR * 2 + 128 * 4;   // 139,776 B (covers rec's ~93 KB too)
    const int MLP_SMEM  = (8192 + 4096) * 4;            // 48 KB
    cudaFuncSetAttribute(gemm0_kernel, cudaFuncAttributeMaxDynamicSharedMemorySize, GEMM_SMEM);
    cudaFuncSetAttribute(layer_kernel, cudaFuncAttributeMaxDynamicSharedMemorySize, GEMM_SMEM);
    cudaFuncSetAttribute(mlp_kernel,   cudaFuncAttributeMaxDynamicSharedMemorySize, MLP_SMEM);

    cudaMemsetAsync(prog, 0, 3 * BATCH * sizeof(int));

    const size_t WSZ = (size_t)GATES * HID;

    // Layer 0 input GEMM (from x) -> bufA
    gemm0_kernel<<<dim3(BATCH * T_STEPS / 128, 4), 256, GEMM_SMEM>>>(
        x, wih, bih, bhh);

    // K0: rec(0) on bufA  +  gemm(1) -> bufB
    layer_kernel<<<NSM, 256, GEMM_SMEM>>>(
        whh, bufA, wih + WSZ, bih + GATES, bhh + GATES, bufB, prog, 1);
    // K1: rec(1) on bufB  +  gemm(2) -> bufA
    layer_kernel<<<NSM, 256, GEMM_SMEM>>>(
        whh + WSZ, bufB, wih + 2 * WSZ, bih + 2 * GATES, bhh + 2 * GATES, bufA,
        prog + BATCH, 1);
    // K2: rec(2) on bufA (no gemm workers)
    layer_kernel<<<BATCH, 256, GEMM_SMEM>>>(
        whh + 2 * WSZ, bufA, nullptr, nullptr, nullptr, nullptr,
        prog + 2 * BATCH, 0);

    mlp_kernel<<<1, 256, MLP_SMEM>>>(w1, b1, w2, b2, w3, b3, (float*)d_out);
}

// round 10
// speedup vs baseline: 1.1099x; 1.1099x over previous
#include <cuda_runtime.h>
#include <cuda_bf16.h>
#include <cstddef>

#define T_STEPS 2048
#define BATCH   64
#define HID     128
#define GATES   512          // 4*HID
#define RK      96           // k-values in registers (as pairs)
#define RKP     (RK/2)       // 48 register pairs
#define SK      (HID - RK)   // 32 k-values in smem
#define SKP     (SK/2)       // 16 smem pairs
#define NSM     148
#define NWORK   (NSM - BATCH)   // 84 gemm worker CTAs

typedef unsigned long long ull;

// ---- packed fp32x2 helpers (sm_100+) --------------------------------------
__device__ __forceinline__ ull ffma2(ull a, ull b, ull c) {
    ull d;
    asm("fma.rn.f32x2 %0, %1, %2, %3;" : "=l"(d) : "l"(a), "l"(b), "l"(c));
    return d;
}
__device__ __forceinline__ ull pack2(float lo, float hi) {
    ull r; asm("mov.b64 %0, {%1, %2};" : "=l"(r) : "f"(lo), "f"(hi)); return r;
}
__device__ __forceinline__ float2 unpack2(ull v) {
    float2 f; asm("mov.b64 {%0, %1}, %2;" : "=f"(f.x), "=f"(f.y) : "l"(v)); return f;
}

// Scratch (device globals; no allocations allowed)
__device__ float g_gxA[(size_t)BATCH * T_STEPS * GATES];  // 256 MB
__device__ float g_gxB[(size_t)BATCH * T_STEPS * GATES];  // 256 MB
__device__ float g_h  [(size_t)BATCH * T_STEPS * HID];    // 64 MB
__device__ int   g_prog[3 * BATCH];                        // rec progress per layer

// ---------------------------------------------------------------------------
// GEMM tile machinery (bf16 3-product split, fp32 acc, ldmatrix)
// ---------------------------------------------------------------------------
#define SR 136   // padded bf16 row stride

__device__ __forceinline__ void mma_bf16(float* d, const unsigned* a, const unsigned* b) {
    asm volatile(
        "mma.sync.aligned.m16n8k16.row.col.f32.bf16.bf16.f32 "
        "{%0,%1,%2,%3}, {%4,%5,%6,%7}, {%8,%9}, {%0,%1,%2,%3};"
        : "+f"(d[0]), "+f"(d[1]), "+f"(d[2]), "+f"(d[3])
        : "r"(a[0]), "r"(a[1]), "r"(a[2]), "r"(a[3]), "r"(b[0]), "r"(b[1]));
}
__device__ __forceinline__ void ldsm_x4(unsigned* r, unsigned addr) {
    asm volatile("ldmatrix.sync.aligned.m8n8.x4.shared.b16 {%0,%1,%2,%3}, [%4];"
                 : "=r"(r[0]), "=r"(r[1]), "=r"(r[2]), "=r"(r[3]) : "r"(addr));
}

// One 128x128 tile: out[brow..][bcol..] = A[brow..][0..128) * W[bcol..][.]^T + bias
__device__ void gemm_tile(const float* __restrict__ A, const float* __restrict__ W,
                          const float* __restrict__ bih, const float* __restrict__ bhh,
                          float* __restrict__ out, int brow, int bcol, char* gsm)
{
    __nv_bfloat16* a_hi = (__nv_bfloat16*)gsm;                  // [128][SR]
    __nv_bfloat16* a_lo = a_hi + 128 * SR;
    __nv_bfloat16* w_hi = a_lo + 128 * SR;
    __nv_bfloat16* w_lo = w_hi + 128 * SR;
    float*         bias_s = (float*)(w_lo + 128 * SR);          // [128]

    const int tid = threadIdx.x;
    if (tid < 128) bias_s[tid] = bih[bcol + tid] + bhh[bcol + tid];

    {
        const int row = tid >> 1;
        const int cb  = (tid & 1) * 64;
        const float* Ar = A + (size_t)(brow + row) * HID + cb;
        const float* Wr = W + (size_t)(bcol + row) * HID + cb;
        __nv_bfloat16* ah = a_hi + row * SR + cb;
        __nv_bfloat16* al = a_lo + row * SR + cb;
        __nv_bfloat16* wh = w_hi + row * SR + cb;
        __nv_bfloat16* wl = w_lo + row * SR + cb;
#pragma unroll 4
        for (int c = 0; c < 64; c += 4) {
            float4 v = *(const float4*)(Ar + c);
            __nv_bfloat16 hx = __float2bfloat16_rn(v.x);
            __nv_bfloat16 hy = __float2bfloat16_rn(v.y);
            __nv_bfloat16 hz = __float2bfloat16_rn(v.z);
            __nv_bfloat16 hw = __float2bfloat16_rn(v.w);
            __nv_bfloat162 H0; H0.x = hx; H0.y = hy;
            __nv_bfloat162 H1; H1.x = hz; H1.y = hw;
            __nv_bfloat162 L0 = __floats2bfloat162_rn(v.x - __bfloat162float(hx),
                                                      v.y - __bfloat162float(hy));
            __nv_bfloat162 L1 = __floats2bfloat162_rn(v.z - __bfloat162float(hz),
                                                      v.w - __bfloat162float(hw));
            *(__nv_bfloat162*)(ah + c)     = H0;
            *(__nv_bfloat162*)(ah + c + 2) = H1;
            *(__nv_bfloat162*)(al + c)     = L0;
            *(__nv_bfloat162*)(al + c + 2) = L1;

            float4 u = *(const float4*)(Wr + c);
            __nv_bfloat16 gx = __float2bfloat16_rn(u.x);
            __nv_bfloat16 gy = __float2bfloat16_rn(u.y);
            __nv_bfloat16 gz = __float2bfloat16_rn(u.z);
            __nv_bfloat16 gw = __float2bfloat16_rn(u.w);
            __nv_bfloat162 G0; G0.x = gx; G0.y = gy;
            __nv_bfloat162 G1; G1.x = gz; G1.y = gw;
            __nv_bfloat162 M0 = __floats2bfloat162_rn(u.x - __bfloat162float(gx),
                                                      u.y - __bfloat162float(gy));
            __nv_bfloat162 M1 = __floats2bfloat162_rn(u.z - __bfloat162float(gz),
                                                      u.w - __bfloat162float(gw));
            *(__nv_bfloat162*)(wh + c)     = G0;
            *(__nv_bfloat162*)(wh + c + 2) = G1;
            *(__nv_bfloat162*)(wl + c)     = M0;
            *(__nv_bfloat162*)(wl + c + 2) = M1;
        }
    }
    __syncthreads();

    const int wid    = tid >> 5;
    const int lane   = tid & 31;
    const int warp_m = wid >> 1;
    const int warp_n = wid & 1;
    const int m_base = warp_m * 32;
    const int n_base = warp_n * 64;

    const unsigned a_hi_s = (unsigned)__cvta_generic_to_shared(a_hi);
    const unsigned a_lo_s = (unsigned)__cvta_generic_to_shared(a_lo);
    const unsigned w_hi_s = (unsigned)__cvta_generic_to_shared(w_hi);
    const unsigned w_lo_s = (unsigned)__cvta_generic_to_shared(w_lo);

    const int arow  = m_base + (lane & 15);
    const int akoff = (lane >> 4) * 8;
    const int gsel  = lane >> 3;
    const int brow_ = n_base + ((gsel >> 1) & 1) * 8 + (lane & 7);
    const int bkoff = (gsel & 1) * 8;

    float d[2][8][4];
#pragma unroll
    for (int mi = 0; mi < 2; mi++)
#pragma unroll
        for (int ni = 0; ni < 8; ni++)
#pragma unroll
            for (int e = 0; e < 4; e++) d[mi][ni][e] = 0.f;

#pragma unroll
    for (int k0 = 0; k0 < HID; k0 += 16) {
        unsigned ah[2][4], al[2][4];
#pragma unroll
        for (int mi = 0; mi < 2; mi++) {
            unsigned off = (unsigned)(((arow + mi * 16) * SR + akoff + k0) * 2);
            ldsm_x4(ah[mi], a_hi_s + off);
            ldsm_x4(al[mi], a_lo_s + off);
        }
        unsigned bh[4][4], bl[4][4];
#pragma unroll
        for (int nb = 0; nb < 4; nb++) {
            unsigned off = (unsigned)(((brow_ + nb * 16) * SR + bkoff + k0) * 2);
            ldsm_x4(bh[nb], w_hi_s + off);
            ldsm_x4(bl[nb], w_lo_s + off);
        }
#pragma unroll
        for (int mi = 0; mi < 2; mi++)
#pragma unroll
            for (int nb = 0; nb < 4; nb++) {
                mma_bf16(d[mi][2 * nb],     ah[mi], &bh[nb][0]);
                mma_bf16(d[mi][2 * nb],     ah[mi], &bl[nb][0]);
                mma_bf16(d[mi][2 * nb],     al[mi], &bh[nb][0]);
                mma_bf16(d[mi][2 * nb + 1], ah[mi], &bh[nb][2]);
                mma_bf16(d[mi][2 * nb + 1], ah[mi], &bl[nb][2]);
                mma_bf16(d[mi][2 * nb + 1], al[mi], &bh[nb][2]);
            }
    }

    const int tr = lane >> 2;
    const int tc = (lane & 3) * 2;
#pragma unroll
    for (int mi = 0; mi < 2; mi++) {
        int gr0 = brow + m_base + mi * 16 + tr;
#pragma unroll
        for (int ni = 0; ni < 8; ni++) {
            int lc = n_base + ni * 8 + tc;
            float2 bv = *(const float2*)&bias_s[lc];
            float2 o0 = {d[mi][ni][0] + bv.x, d[mi][ni][1] + bv.y};
            float2 o1 = {d[mi][ni][2] + bv.x, d[mi][ni][3] + bv.y};
            *(float2*)(out + (size_t)gr0 * GATES + bcol + lc)       = o0;
            *(float2*)(out + (size_t)(gr0 + 8) * GATES + bcol + lc) = o1;
        }
    }
}

// Standalone layer-0 GEMM over the whole input
__global__ __launch_bounds__(256) void gemm0_kernel(
    const float* __restrict__ A, const float* __restrict__ W,
    const float* __restrict__ bih, const float* __restrict__ bhh)
{
    extern __shared__ char gsm[];
    gemm_tile(A, W, bih, bhh, g_gxA, blockIdx.x * 128, blockIdx.y * 128, gsm);
}

// ---------------------------------------------------------------------------
// Recurrence body — exact R3 structure (measured best: 1.498 ms/layer).
// One CTA per batch row, 256 threads, thread owns gate rows tid and tid+256.
// Weight pairs [0,RKP) in registers, [RKP,64) in smem pair-major
// (ws2[p*512+r], LDS.64 conflict-free). Two barriers/step, gates via smem.
// ---------------------------------------------------------------------------
__device__ __forceinline__ float sigm(float x) {
    return __fdividef(1.f, 1.f + __expf(-x));
}
__device__ __forceinline__ float tanh_fast(float x) {
    float e = __expf(2.f * x);
    return 1.f - __fdividef(2.f, e + 1.f);
}

__device__ void rec_body(const float* __restrict__ whh, const float* __restrict__ gx,
                         int* __restrict__ prog, int b, char* smraw)
{
    ull*   ws2 = (ull*)smraw;                    // [SKP][512] pair-major weight pairs
    float* g_s = (float*)(ws2 + SKP * 512);      // 512 gate pre-activations
    float* h_s = g_s + GATES;                    // 128 hidden state

    const int tid = threadIdx.x;
    const int r0  = tid;
    const int r1  = tid + 256;

    ull wa2[RKP], wb2[RKP];
    {
        const ull* wp0 = (const ull*)(whh + (size_t)r0 * HID);
        const ull* wp1 = (const ull*)(whh + (size_t)r1 * HID);
#pragma unroll
        for (int q = 0; q < RKP; q++) { wa2[q] = wp0[q]; wb2[q] = wp1[q]; }
    }
    for (int idx = tid; idx < SKP * 512; idx += 256) {
        int r = idx & 511, p = idx >> 9;
        ws2[idx] = ((const ull*)(whh + (size_t)r * HID))[RKP + p];
    }
    if (tid < HID) h_s[tid] = 0.f;
    float c = 0.f;
    __syncthreads();

    const float* gxb = gx  + (size_t)b * T_STEPS * GATES;
    float*       hb  = g_h + (size_t)b * T_STEPS * HID;

    float nga = gxb[r0];
    float ngb = gxb[r1];

    for (int t = 0; t < T_STEPS; t++) {
        ull acc0 = pack2(nga, 0.f);
        ull acc1 = pack2(ngb, 0.f);
        if (t + 1 < T_STEPS) {
            nga = __ldg(gxb + (size_t)(t + 1) * GATES + r0);
            ngb = __ldg(gxb + (size_t)(t + 1) * GATES + r1);
        }
        const ull* h2 = (const ull*)h_s;   // 64 packed h pairs (broadcast LDS.64)
#pragma unroll
        for (int q = 0; q < RKP; q++) {
            ull hp = h2[q];
            acc0 = ffma2(hp, wa2[q], acc0);
            acc1 = ffma2(hp, wb2[q], acc1);
        }
#pragma unroll
        for (int p = 0; p < SKP; p++) {
            ull hp = h2[RKP + p];
            acc0 = ffma2(hp, ws2[p * 512 + r0], acc0);
            acc1 = ffma2(hp, ws2[p * 512 + r1], acc1);
        }
        float2 v0 = unpack2(acc0);
        float2 v1 = unpack2(acc1);
        g_s[r0] = v0.x + v0.y;
        g_s[r1] = v1.x + v1.y;
        __syncthreads();
        if (tid < 128) {
            float i_ = sigm(g_s[tid]);
            float f_ = sigm(g_s[tid + 128]);
            float g_ = tanh_fast(g_s[tid + 256]);
            float o_ = sigm(g_s[tid + 384]);
            c = fmaf(f_, c, i_ * g_);
            float hv = o_ * tanh_fast(c);
            h_s[tid] = hv;
            hb[(size_t)t * HID + tid] = hv;
        }
        __syncthreads();
        if ((t & 63) == 63 && tid == 0) {
            __threadfence();
            atomicExch(prog + b, t + 1);
        }
    }
}

// ---------------------------------------------------------------------------
// GEMM worker: persistent CTA computing next layer's gx tiles, paced by the
// recurrence's progress counters. Tiles ordered t-chunk-major.
// ---------------------------------------------------------------------------
__device__ void gemm_worker(const float* __restrict__ W,
                            const float* __restrict__ bih, const float* __restrict__ bhh,
                            float* __restrict__ out, int* __restrict__ prog,
                            int worker, char* gsm)
{
    const int tid = threadIdx.x;
    const int NT = 16 * BATCH * 4;   // 16 t-chunks * 64 batch * 4 col tiles = 4096
    for (int idx = worker; idx < NT; idx += NWORK) {
        int tt  = idx >> 8;          // 0..15
        int rem = idx & 255;
        int b   = rem >> 2;          // 0..63
        int cy  = rem & 3;           // 0..3
        int need = (tt + 1) * 128;
        if (tid == 0) {
            unsigned v;
            while (true) {
                asm volatile("ld.global.cg.u32 %0, [%1];" : "=r"(v) : "l"(prog + b));
                if ((int)v >= need) break;
                __nanosleep(256);
            }
            __threadfence();
        }
        __syncthreads();
        gemm_tile(g_h, W, bih, bhh, out, b * T_STEPS + tt * 128, cy * 128, gsm);
        __syncthreads();
    }
}

// ---------------------------------------------------------------------------
// Combined layer kernel: blocks [0,64) run the recurrence for layer l,
// blocks [64,148) stream next layer's input GEMM.
// ---------------------------------------------------------------------------
__global__ __launch_bounds__(256, 1) void layer_kernel(
    const float* __restrict__ whh, const float* __restrict__ gx_in,
    const float* __restrict__ wih_next, const float* __restrict__ bih_next,
    const float* __restrict__ bhh_next, float* __restrict__ gx_out,
    int* __restrict__ prog, int do_gemm)
{
    extern __shared__ char smraw[];
    if (blockIdx.x < BATCH) {
        rec_body(whh, gx_in, prog, blockIdx.x, smraw);
    } else if (do_gemm) {
        gemm_worker(wih_next, bih_next, bhh_next, gx_out, prog,
                    blockIdx.x - BATCH, smraw);
    }
}

// ---------------------------------------------------------------------------
// MLP head: h_last[64,128] -> 64 -> 32 -> 10 (all linear)
// ---------------------------------------------------------------------------
__global__ __launch_bounds__(256) void mlp_kernel(
    const float* __restrict__ w1, const float* __restrict__ b1,
    const float* __restrict__ w2, const float* __restrict__ b2,
    const float* __restrict__ w3, const float* __restrict__ b3,
    float* __restrict__ out)
{
    extern __shared__ float sm[];
    float* hs = sm;          // 64*128, later reused for y2 (64*32)
    float* y1 = sm + 8192;   // 64*64

    const int tid = threadIdx.x;
    for (int idx = tid; idx < 8192; idx += 256) {
        int b = idx >> 7, j = idx & 127;
        hs[idx] = g_h[(size_t)b * T_STEPS * HID + (size_t)(T_STEPS - 1) * HID + j];
    }
    __syncthreads();
    for (int idx = tid; idx < 4096; idx += 256) {
        int b = idx >> 6, o = idx & 63;
        float s = b1[o];
#pragma unroll 8
        for (int k = 0; k < 128; k++) s = fmaf(hs[b * 128 + k], w1[o * 128 + k], s);
        y1[idx] = s;
    }
    __syncthreads();
    for (int idx = tid; idx < 2048; idx += 256) {
        int b = idx >> 5, o = idx & 31;
        float s = b2[o];
#pragma unroll 8
        for (int k = 0; k < 64; k++) s = fmaf(y1[b * 64 + k], w2[o * 64 + k], s);
        hs[idx] = s;  // reuse hs as y2 [64,32]
    }
    __syncthreads();
    for (int idx = tid; idx < 640; idx += 256) {
        int b = idx / 10, o = idx % 10;
        float s = b3[o];
#pragma unroll
        for (int k = 0; k < 32; k++) s = fmaf(hs[b * 32 + k], w3[o * 32 + k], s);
        out[idx] = s;
    }
}

// ---------------------------------------------------------------------------
extern "C" void kernel_launch(void* const* d_in, const int* in_sizes, int n_in,
                              void* d_out, int out_size)
{
    (void)in_sizes; (void)n_in; (void)out_size;
    const float* x   = (const float*)d_in[0];
    const float* wih = (const float*)d_in[1];
    const float* whh = (const float*)d_in[2];
    const float* bih = (const float*)d_in[3];
    const float* bhh = (const float*)d_in[4];
    const float* w1  = (const float*)d_in[5];
    const float* b1  = (const float*)d_in[6];
    const float* w2  = (const float*)d_in[7];
    const float* b2  = (const float*)d_in[8];
    const float* w3  = (const float*)d_in[9];
    const float* b3  = (const float*)d_in[10];

    void *pA = nullptr, *pB = nullptr, *pP = nullptr;
    cudaGetSymbolAddress(&pA, g_gxA);
    cudaGetSymbolAddress(&pB, g_gxB);
    cudaGetSymbolAddress(&pP, g_prog);
    float* bufA = (float*)pA;
    float* bufB = (float*)pB;
    int*   prog = (int*)pP;

    const int GEMM_SMEM = 4 * 128 * SR * 2 + 128 * 4;   // 139,776 B (covers rec's ~68 KB too)
    const int MLP_SMEM  = (8192 + 4096) * 4;            // 48 KB
    cudaFuncSetAttribute(gemm0_kernel, cudaFuncAttributeMaxDynamicSharedMemorySize, GEMM_SMEM);
    cudaFuncSetAttribute(layer_kernel, cudaFuncAttributeMaxDynamicSharedMemorySize, GEMM_SMEM);
    cudaFuncSetAttribute(mlp_kernel,   cudaFuncAttributeMaxDynamicSharedMemorySize, MLP_SMEM);

    cudaMemsetAsync(prog, 0, 3 * BATCH * sizeof(int));

    const size_t WSZ = (size_t)GATES * HID;

    // Layer 0 input GEMM (from x) -> bufA
    gemm0_kernel<<<dim3(BATCH * T_STEPS / 128, 4), 256, GEMM_SMEM>>>(
        x, wih, bih, bhh);

    // K0: rec(0) on bufA  +  gemm(1) -> bufB
    layer_kernel<<<NSM, 256, GEMM_SMEM>>>(
        whh, bufA, wih + WSZ, bih + GATES, bhh + GATES, bufB, prog, 1);
    // K1: rec(1) on bufB  +  gemm(2) -> bufA
    layer_kernel<<<NSM, 256, GEMM_SMEM>>>(
        whh + WSZ, bufB, wih + 2 * WSZ, bih + 2 * GATES, bhh + 2 * GATES, bufA,
        prog + BATCH, 1);
    // K2: rec(2) on bufA (no gemm workers)
    layer_kernel<<<BATCH, 256, GEMM_SMEM>>>(
        whh + 2 * WSZ, bufA, nullptr, nullptr, nullptr, nullptr,
        prog + 2 * BATCH, 0);

    mlp_kernel<<<1, 256, MLP_SMEM>>>(w1, b1, w2, b2, w3, b3, (float*)d_out);
}